// round 9
// baseline (speedup 1.0000x reference)
#include <cuda_runtime.h>
#include <math.h>
#include <stdint.h>

#define D     1024
#define B     16
#define T     1024
#define G     128      // persistent CTAs (one per SM)
#define HALF  64       // CTAs per batch-half barrier group
#define DPC   16       // d's per CTA
#define BPC   8        // b's per CTA
#define NTHR  512      // 16 warps: 2 d-groups (8d) x 8 k-slices (128k)

#define MAXR  0.999f
#define EPSF  1e-8f

typedef unsigned long long u64;

// ---------------- device scratch ----------------
__device__ float    g_WhT[D * D];
__device__ float    g_hbuf[2][B * D];
__device__ float    g_sigma;
__device__ unsigned g_bar[2];           // one barrier per batch-half

// ---------------- packed fp32x2 helpers ----------------
__device__ __forceinline__ u64 dup2(float w) {
    u64 r; asm("mov.b64 %0, {%1, %1};" : "=l"(r) : "f"(w)); return r;
}
__device__ __forceinline__ u64 pack2(float lo, float hi) {
    u64 r; asm("mov.b64 %0, {%1, %2};" : "=l"(r) : "f"(lo), "f"(hi)); return r;
}
__device__ __forceinline__ void fma2(u64& a, u64 w, u64 x) {
    asm("fma.rn.f32x2 %0, %1, %2, %0;" : "+l"(a) : "l"(w), "l"(x));
}
__device__ __forceinline__ u64 addp(u64 a, u64 b) {
    u64 c; asm("add.rn.f32x2 %0, %1, %2;" : "=l"(c) : "l"(a), "l"(b)); return c;
}
__device__ __forceinline__ float lo32(u64 a) { return __uint_as_float((unsigned)(a & 0xffffffffull)); }
__device__ __forceinline__ float hi32(u64 a) { return __uint_as_float((unsigned)(a >> 32)); }

// coherent (L2) vector load — for cross-SM mutable buffers
__device__ __forceinline__ float4 ldcg4(const float4* p) {
    float4 v;
    asm volatile("ld.global.cg.v4.f32 {%0,%1,%2,%3}, [%4];"
                 : "=f"(v.x), "=f"(v.y), "=f"(v.z), "=f"(v.w) : "l"(p));
    return v;
}

// ---------------- init ----------------
__global__ void k_init(const float* __restrict__ h0, float* __restrict__ hall0) {
    int i = blockIdx.x * blockDim.x + threadIdx.x;
    if (i < 2) g_bar[i] = 0u;
    if (i < B * D) hall0[i] = h0[i];
}

// ---------------- transpose for power iteration ----------------
__global__ void k_transpose(const float* __restrict__ A) {
    __shared__ float tile[32][33];
    int bx = blockIdx.x * 32, by = blockIdx.y * 32;
    int tx = threadIdx.x, ty = threadIdx.y;
#pragma unroll
    for (int r = 0; r < 32; r += 8)
        tile[ty + r][tx] = A[(size_t)(by + ty + r) * D + bx + tx];
    __syncthreads();
#pragma unroll
    for (int r = 0; r < 32; r += 8)
        g_WhT[(size_t)(bx + ty + r) * D + by + tx] = tile[tx][ty + r];
}

// ---------------- power iteration ----------------
__device__ __forceinline__ float blk_reduce(float v, float* sred) {
#pragma unroll
    for (int s = 16; s; s >>= 1) v += __shfl_xor_sync(0xffffffffu, v, s);
    int w = threadIdx.x >> 5;
    if ((threadIdx.x & 31) == 0) sred[w] = v;
    __syncthreads();
    if (threadIdx.x < 32) {
        float r = sred[threadIdx.x];
#pragma unroll
        for (int s = 16; s; s >>= 1) r += __shfl_xor_sync(0xffffffffu, r, s);
        if (threadIdx.x == 0) sred[0] = r;
    }
    __syncthreads();
    float out = sred[0];
    __syncthreads();
    return out;
}

__global__ void k_power(const float* __restrict__ Wh, const float* __restrict__ u0) {
    __shared__ float sv[D];
    __shared__ float sred[32];
    const int tid = threadIdx.x;
    float u = u0[tid];
    float v = 0.f;
    for (int it = 0; it < 3; ++it) {
        sv[tid] = u; __syncthreads();
        float acc = 0.f;
#pragma unroll 8
        for (int j = 0; j < D; ++j) acc += Wh[(size_t)j * D + tid] * sv[j];
        __syncthreads();
        float nn = blk_reduce(acc * acc, sred);
        v = acc / (sqrtf(nn) + EPSF);

        sv[tid] = v; __syncthreads();
        acc = 0.f;
#pragma unroll 8
        for (int j = 0; j < D; ++j) acc += g_WhT[(size_t)j * D + tid] * sv[j];
        __syncthreads();
        nn = blk_reduce(acc * acc, sred);
        u = acc / (sqrtf(nn) + EPSF);
    }
    sv[tid] = v; __syncthreads();
    float tvec = 0.f;
#pragma unroll 8
    for (int j = 0; j < D; ++j) tvec += g_WhT[(size_t)j * D + tid] * sv[j];
    __syncthreads();
    float s = blk_reduce(u * tvec, sred);
    if (tid == 0) g_sigma = fabsf(s);
}

// ---------------- GEMV tile from SMEM V: 8d x 8b per warp, 128 k ----------------
__device__ __forceinline__ void mv_smem(const float* __restrict__ W,  // [DPC][D]
                                        const float* __restrict__ V,  // [BPC][D] smem
                                        u64* __restrict__ acc,
                                        int dbase, int kbase, int lane) {
#pragma unroll
    for (int i = 0; i < 4; ++i) {
        const int k = kbase + 32 * i + lane;
        u64 x0 = pack2(V[0 * D + k], V[1 * D + k]);
        u64 x1 = pack2(V[2 * D + k], V[3 * D + k]);
        u64 x2 = pack2(V[4 * D + k], V[5 * D + k]);
        u64 x3 = pack2(V[6 * D + k], V[7 * D + k]);
#pragma unroll
        for (int dd = 0; dd < 8; ++dd) {
            u64 w = dup2(W[(dbase + dd) * D + k]);
            fma2(acc[dd * 4 + 0], w, x0);
            fma2(acc[dd * 4 + 1], w, x1);
            fma2(acc[dd * 4 + 2], w, x2);
            fma2(acc[dd * 4 + 3], w, x3);
        }
    }
}

// ---------------- GEMV tile with V from GMEM (immutable input) ----------------
__device__ __forceinline__ void mv_gmem(const float* __restrict__ W,   // [DPC][D] smem
                                        const float* __restrict__ V,   // gmem, rows b0.., [b][D]
                                        u64* __restrict__ acc,
                                        int dbase, int kbase, int lane) {
#pragma unroll
    for (int i = 0; i < 4; ++i) {
        const int k = kbase + 32 * i + lane;
        float v0 = __ldg(V + 0 * D + k), v1 = __ldg(V + 1 * D + k);
        float v2 = __ldg(V + 2 * D + k), v3 = __ldg(V + 3 * D + k);
        float v4 = __ldg(V + 4 * D + k), v5 = __ldg(V + 5 * D + k);
        float v6 = __ldg(V + 6 * D + k), v7 = __ldg(V + 7 * D + k);
        u64 x0 = pack2(v0, v1);
        u64 x1 = pack2(v2, v3);
        u64 x2 = pack2(v4, v5);
        u64 x3 = pack2(v6, v7);
#pragma unroll
        for (int dd = 0; dd < 8; ++dd) {
            u64 w = dup2(W[(dbase + dd) * D + k]);
            fma2(acc[dd * 4 + 0], w, x0);
            fma2(acc[dd * 4 + 1], w, x1);
            fma2(acc[dd * 4 + 2], w, x2);
            fma2(acc[dd * 4 + 3], w, x3);
        }
    }
}

// distributing tree reduce: lane L ends owning sum-over-lanes of acc[L]
#define RED_LEVEL(m, n)                                                     \
    {                                                                       \
        const bool up = (lane & (m)) != 0;                                  \
        _Pragma("unroll")                                                   \
        for (int j = 0; j < (n); ++j) {                                     \
            u64 send = up ? acc[j] : acc[j + (n)];                          \
            u64 recv = __shfl_xor_sync(0xffffffffu, send, (m));             \
            acc[j] = addp(up ? acc[j + (n)] : acc[j], recv);                \
        }                                                                   \
    }

// ---------------- persistent fused recurrence ----------------
__global__ void __launch_bounds__(NTHR, 1)
k_persist(const float* __restrict__ x, const float* __restrict__ z,
          const float* __restrict__ h0, const float* __restrict__ Wx,
          const float* __restrict__ Wh, const float* __restrict__ logr,
          const float* __restrict__ bias, float* __restrict__ out) {
    extern __shared__ float sm[];
    float* Wx_s  = sm;                     // [DPC][D]   64 KB
    float* Wh_s  = Wx_s + DPC * D;         // [DPC][D]   64 KB (pre-scaled)
    float* h_s   = Wh_s + DPC * D;         // [BPC][D]   32 KB
    u64*   red_s = (u64*)(h_s + BPC * D);  // [8][64]     4 KB

    const int cta = blockIdx.x;
    const int d0 = (cta >> 1) * DPC;
    const int bg = cta & 1;               // batch-half group
    const int b0 = bg * BPC;
    const int tid = threadIdx.x;
    const int wid = tid >> 5;             // 0..15
    const int lane = tid & 31;
    const int dg = wid >> 3;              // d-group 0/1
    const int ks = wid & 7;               // k-slice 0..7
    const int dbase = dg * 8;
    const int kbase = ks * 128;

    // ---- load weight tiles; pre-scale W_h rows by radii[d]/(sigma+eps) ----
    const float sig = g_sigma + EPSF;
    for (int i = tid; i < DPC * D / 4; i += NTHR) {
        int idx = i * 4;
        int dd = idx >> 10;
        int k = idx & (D - 1);
        int dglob = d0 + dd;
        *(float4*)(Wx_s + dd * D + k) = *(const float4*)(Wx + (size_t)dglob * D + k);
        float r = (MAXR / (1.f + expf(-logr[dglob]))) / sig;
        float4 m = *(const float4*)(Wh + (size_t)dglob * D + k);
        m.x *= r; m.y *= r; m.z *= r; m.w *= r;
        *(float4*)(Wh_s + dd * D + k) = m;
    }
    __syncthreads();   // *** weights visible to ALL warps before any smem-weight read ***

    float* outs_ptr = out;                        // [T][B][D]
    float* hall_ptr = out + (size_t)T * B * D;    // [T+1][B][D]

    // epilogue mapping (tid < 128): consecutive tid -> consecutive d
    const int dl = tid & 15;
    const int bl = (tid >> 4) & 7;
    const size_t eoff = (size_t)(b0 + bl) * D + (d0 + dl);
    const float my_bias = bias[d0 + dl];
    const int epi_p = (dl >> 3) * 32 + (dl & 7) * 4 + (bl >> 1);
    const int epi_half = bl & 1;

    volatile unsigned* barp = &g_bar[bg];

    u64 acc[32];

    // ---- step 0 x-part (independent of h) ----
#pragma unroll
    for (int i = 0; i < 32; ++i) acc[i] = 0ull;
    mv_gmem(Wx_s, x + (size_t)b0 * D, acc, dbase, kbase, lane);
    float zreg = (tid < 128) ? z[eoff] : 0.f;

    for (int t = 0; t < T; ++t) {
        // ---- wait for step t-1 (this batch-half only) ----
        if (t > 0) {
            if (tid == 0) {
                unsigned target = (unsigned)t * HALF;
                while (*barp < target) {}
                __threadfence();
            }
            __syncthreads();
        }

        // ---- stage h_prev: linear coalesced 32 KB copy (coherent L2 path) ----
        {
            const float* hsrc = ((t == 0) ? h0 : g_hbuf[(t - 1) & 1]) + (size_t)b0 * D;
#pragma unroll
            for (int i = 0; i < 4; ++i) {
                int idx = tid + i * NTHR;
                *(float4*)(h_s + idx * 4) = ldcg4((const float4*)(hsrc) + idx);
            }
        }
        __syncthreads();

        // ---- recurrent GEMV: acc += W_heff * h_prev ----
        mv_smem(Wh_s, h_s, acc, dbase, kbase, lane);

        // ---- tree reduce: lane L owns acc[L] ----
        RED_LEVEL(16, 16)
        RED_LEVEL(8, 8)
        RED_LEVEL(4, 4)
        RED_LEVEL(2, 2)
        RED_LEVEL(1, 1)
        red_s[ks * 64 + dg * 32 + lane] = acc[0];
        __syncthreads();

        // ---- epilogue: sum 8 k-slices, tanh, publish, gate ----
        if (tid < 128) {
            u64 s0 = addp(red_s[0 * 64 + epi_p], red_s[1 * 64 + epi_p]);
            u64 s1 = addp(red_s[2 * 64 + epi_p], red_s[3 * 64 + epi_p]);
            u64 s2 = addp(red_s[4 * 64 + epi_p], red_s[5 * 64 + epi_p]);
            u64 s3 = addp(red_s[6 * 64 + epi_p], red_s[7 * 64 + epi_p]);
            u64 s = addp(addp(s0, s1), addp(s2, s3));
            float pre = (epi_half ? hi32(s) : lo32(s)) + my_bias;
            float hnew = tanhf(pre);
            g_hbuf[t & 1][eoff] = hnew;
            float sil = zreg / (1.f + __expf(-zreg));
            outs_ptr[(size_t)t * B * D + eoff] = hnew * sil;
            hall_ptr[(size_t)(t + 1) * B * D + eoff] = hnew;
        }
        __syncthreads();

        // ---- arrive (release h_new for this batch-half) ----
        if (tid == 0) {
            __threadfence();
            atomicAdd(&g_bar[bg], 1u);
        }

        // ---- shadow: x-part of step t+1 straight from GMEM ----
#pragma unroll
        for (int i = 0; i < 32; ++i) acc[i] = 0ull;
        if (t + 1 < T) {
            mv_gmem(Wx_s, x + (size_t)(t + 1) * B * D + (size_t)b0 * D,
                    acc, dbase, kbase, lane);
            if (tid < 128) zreg = __ldg(z + (size_t)(t + 1) * B * D + eoff);
        }
    }
}

// ---------------- launch ----------------
extern "C" void kernel_launch(void* const* d_in, const int* in_sizes, int n_in,
                              void* d_out, int out_size) {
    const float* x    = (const float*)d_in[0];
    const float* z    = (const float*)d_in[1];
    const float* h0   = (const float*)d_in[2];
    const float* Wx   = (const float*)d_in[3];
    const float* Wh   = (const float*)d_in[4];
    const float* logr = (const float*)d_in[5];
    const float* bias = (const float*)d_in[6];
    const float* u0   = (const float*)d_in[7];
    float* out = (float*)d_out;

    const int smem_bytes = (DPC * D * 2 + BPC * D) * sizeof(float) + 512 * sizeof(u64);
    cudaFuncSetAttribute(k_persist, cudaFuncAttributeMaxDynamicSharedMemorySize,
                         smem_bytes);

    k_init<<<64, 256>>>(h0, out + (size_t)T * B * D);
    k_transpose<<<dim3(D / 32, D / 32), dim3(32, 8)>>>(Wh);
    k_power<<<1, D>>>(Wh, u0);
    k_persist<<<G, NTHR, smem_bytes>>>(x, z, h0, Wx, Wh, logr, bias, out);
}